// round 1
// baseline (speedup 1.0000x reference)
#include <cuda_runtime.h>

#define HID 1024
#define SEQ 512
#define BATCH 2
#define NH 16
#define HD 64
#define ROWS (BATCH*SEQ)
#define NKEY (SEQ*NH)   // 8192 keys per batch

// Scratch (device globals: no allocations allowed)
__device__ float g_q[ROWS*HID];
__device__ float g_k[ROWS*HID];
__device__ float g_v[ROWS*HID];
__device__ float g_att[ROWS*HID];   // scrambled attention output

// ---------------------------------------------------------------------------
// SGEMM: C[1024,1024] = A[1024,1024] @ W[1024,1024] + bias
// BM=BN=128, BK=16, 256 threads, 8x8 per thread (4+4 split), swizzled A smem.
// ---------------------------------------------------------------------------
__device__ __forceinline__ void gemm_body(const float* __restrict__ A,
                                          const float* __restrict__ W,
                                          const float* __restrict__ bias,
                                          float* __restrict__ C)
{
    __shared__ float As[16*128];   // transposed: As[k][m], XOR-swizzled column
    __shared__ float Bs[16*128];   // Bs[k][n]

    const int tid = threadIdx.x;
    const int tx = tid & 15, ty = tid >> 4;
    const int m0 = blockIdx.y * 128, n0 = blockIdx.x * 128;

    float acc[8][8];
    #pragma unroll
    for (int i = 0; i < 8; i++)
        #pragma unroll
        for (int j = 0; j < 8; j++) acc[i][j] = 0.f;

    for (int k0 = 0; k0 < HID; k0 += 16) {
        #pragma unroll
        for (int l = 0; l < 2; l++) {
            int i = tid + l*256;
            // A tile 128x16, transpose into As with swizzle
            int ar = i >> 2, ac = (i & 3) << 2;
            float4 va = *(const float4*)(A + (size_t)(m0+ar)*HID + k0 + ac);
            int col = ar ^ ((i & 3) << 2);
            As[(ac+0)*128 + col] = va.x;
            As[(ac+1)*128 + col] = va.y;
            As[(ac+2)*128 + col] = va.z;
            As[(ac+3)*128 + col] = va.w;
            // B tile 16x128, direct vector copy
            int br = i >> 5, bc = (i & 31) << 2;
            *(float4*)(Bs + br*128 + bc) =
                *(const float4*)(W + (size_t)(k0+br)*HID + n0 + bc);
        }
        __syncthreads();
        #pragma unroll
        for (int kk = 0; kk < 16; kk++) {
            int sw = ((kk >> 2) & 7) << 2;
            float a[8], b[8];
            *(float4*)(a)   = *(const float4*)(As + kk*128 + ((ty*4) ^ sw));
            *(float4*)(a+4) = *(const float4*)(As + kk*128 + ((64 + ty*4) ^ sw));
            *(float4*)(b)   = *(const float4*)(Bs + kk*128 + tx*4);
            *(float4*)(b+4) = *(const float4*)(Bs + kk*128 + 64 + tx*4);
            #pragma unroll
            for (int i = 0; i < 8; i++)
                #pragma unroll
                for (int j = 0; j < 8; j++)
                    acc[i][j] += a[i] * b[j];
        }
        __syncthreads();
    }

    // Epilogue: vectorized float4 stores
    #pragma unroll
    for (int i = 0; i < 8; i++) {
        int m = m0 + ((i < 4) ? (ty*4 + i) : (64 + ty*4 + (i-4)));
        float4 bia0 = *(const float4*)(bias + n0 + tx*4);
        float4 bia1 = *(const float4*)(bias + n0 + 64 + tx*4);
        float4 o0 = make_float4(acc[i][0]+bia0.x, acc[i][1]+bia0.y,
                                acc[i][2]+bia0.z, acc[i][3]+bia0.w);
        float4 o1 = make_float4(acc[i][4]+bia1.x, acc[i][5]+bia1.y,
                                acc[i][6]+bia1.z, acc[i][7]+bia1.w);
        *(float4*)(C + (size_t)m*HID + n0 + tx*4)      = o0;
        *(float4*)(C + (size_t)m*HID + n0 + 64 + tx*4) = o1;
    }
}

__global__ __launch_bounds__(256)
void qkv_kernel(const float* __restrict__ x,
                const float* __restrict__ Wq, const float* __restrict__ bq,
                const float* __restrict__ Wk, const float* __restrict__ bk,
                const float* __restrict__ Wv, const float* __restrict__ bv)
{
    int z = blockIdx.z;
    const float* W    = (z == 0) ? Wq : (z == 1) ? Wk : Wv;
    const float* bias = (z == 0) ? bq : (z == 1) ? bk : bv;
    float* C          = (z == 0) ? g_q : (z == 1) ? g_k : g_v;
    gemm_body(x, W, bias, C);
}

__global__ __launch_bounds__(256)
void oproj_kernel(const float* __restrict__ Wo, const float* __restrict__ bo,
                  float* __restrict__ out)
{
    gemm_body(g_att, Wo, bo, out);
}

// ---------------------------------------------------------------------------
// Flash attention, no-max softmax (scores bounded small).
// Grid: 128 blocks = B(2) x H(16) x Qtiles(4 of 128). 256 threads.
// Per block: Q tile [128 x 64] vs all 8192 keys in 64-key tiles.
// smem: Qs[64][128] (d-major, swizzled), Ks[64][64] (d-major, swizzled),
//       Vs[64][64] (k-major), Ps[128][64]. Total 96 KB dynamic.
// ---------------------------------------------------------------------------
#define ATTN_SMEM ((64*128 + 64*64 + 64*64 + 128*64) * 4)

__global__ __launch_bounds__(256)
void attn_kernel()
{
    extern __shared__ float sm[];
    float* Qs = sm;                 // [64][128]
    float* Ks = sm + 64*128;        // [64][64]
    float* Vs = Ks + 64*64;         // [64][64]
    float* Ps = Vs + 64*64;         // [128][64]

    const int tid = threadIdx.x;
    const int tx = tid & 15, ty = tid >> 4;
    const int bx = blockIdx.x;
    const int b  = bx >> 6;
    const int h  = (bx >> 2) & 15;
    const int s0 = (bx & 3) << 7;

    const float* qb = g_q + (size_t)(b*SEQ + s0)*HID + h*HD;
    const float* kb = g_k + (size_t)b*SEQ*HID;   // [8192, 64] view
    const float* vb = g_v + (size_t)b*SEQ*HID;

    // Load + transpose Q tile (scaled by 1/sqrt(64))
    #pragma unroll
    for (int l = 0; l < 8; l++) {
        int i = tid + l*256;
        int sq = i >> 4, d0 = (i & 15) << 2;
        float4 v = *(const float4*)(qb + (size_t)sq*HID + d0);
        int col = sq ^ (((d0 >> 2) & 7) << 2);
        Qs[(d0+0)*128 + col] = v.x * 0.125f;
        Qs[(d0+1)*128 + col] = v.y * 0.125f;
        Qs[(d0+2)*128 + col] = v.z * 0.125f;
        Qs[(d0+3)*128 + col] = v.w * 0.125f;
    }

    float Oacc[8][4];
    float lsum[8];
    int   r[8];
    #pragma unroll
    for (int i = 0; i < 8; i++) {
        lsum[i] = 0.f;
        r[i] = (i < 4) ? (ty*4 + i) : (64 + ty*4 + (i-4));
        #pragma unroll
        for (int j = 0; j < 4; j++) Oacc[i][j] = 0.f;
    }

    for (int jt = 0; jt < NKEY/64; jt++) {
        const float* kp = kb + (size_t)jt*64*HD;
        const float* vp = vb + (size_t)jt*64*HD;

        __syncthreads();   // prev iter's Ks/Vs/Ps reads done
        #pragma unroll
        for (int l = 0; l < 4; l++) {
            int i = tid + l*256;
            int kk = i >> 4, d0 = (i & 15) << 2;
            float4 kv = *(const float4*)(kp + kk*HD + d0);
            int col = kk ^ (((d0 >> 2) & 7) << 2);
            Ks[(d0+0)*64 + col] = kv.x;
            Ks[(d0+1)*64 + col] = kv.y;
            Ks[(d0+2)*64 + col] = kv.z;
            Ks[(d0+3)*64 + col] = kv.w;
            *(float4*)(Vs + kk*64 + d0) = *(const float4*)(vp + kk*HD + d0);
        }
        __syncthreads();

        // S = Q @ K^T  (thread tile 8q x 4k)
        float s_[8][4];
        #pragma unroll
        for (int i = 0; i < 8; i++)
            #pragma unroll
            for (int j = 0; j < 4; j++) s_[i][j] = 0.f;

        #pragma unroll 8
        for (int d = 0; d < 64; d++) {
            int sw = ((d >> 2) & 7) << 2;
            float a[8], bb[4];
            *(float4*)(a)    = *(const float4*)(Qs + d*128 + ((ty*4) ^ sw));
            *(float4*)(a+4)  = *(const float4*)(Qs + d*128 + ((64 + ty*4) ^ sw));
            *(float2*)(bb)   = *(const float2*)(Ks + d*64 + ((tx*2) ^ sw));
            *(float2*)(bb+2) = *(const float2*)(Ks + d*64 + ((32 + tx*2) ^ sw));
            #pragma unroll
            for (int i = 0; i < 8; i++)
                #pragma unroll
                for (int j = 0; j < 4; j++)
                    s_[i][j] += a[i] * bb[j];
        }

        // P = exp(S); accumulate row sums; stage P in smem
        #pragma unroll
        for (int i = 0; i < 8; i++) {
            float p0 = __expf(s_[i][0]);
            float p1 = __expf(s_[i][1]);
            float p2 = __expf(s_[i][2]);
            float p3 = __expf(s_[i][3]);
            lsum[i] += (p0 + p1) + (p2 + p3);
            *(float2*)(Ps + r[i]*64 + tx*2)      = make_float2(p0, p1);
            *(float2*)(Ps + r[i]*64 + 32 + tx*2) = make_float2(p2, p3);
        }
        __syncthreads();

        // O += P @ V  (float4 P chunks to stay off the smem ceiling)
        #pragma unroll 4
        for (int k4 = 0; k4 < 64; k4 += 4) {
            float a4[8][4];
            #pragma unroll
            for (int i = 0; i < 8; i++)
                *(float4*)(a4[i]) = *(const float4*)(Ps + r[i]*64 + k4);
            #pragma unroll
            for (int u = 0; u < 4; u++) {
                float bb[4];
                *(float2*)(bb)   = *(const float2*)(Vs + (k4+u)*64 + tx*2);
                *(float2*)(bb+2) = *(const float2*)(Vs + (k4+u)*64 + 32 + tx*2);
                #pragma unroll
                for (int i = 0; i < 8; i++)
                    #pragma unroll
                    for (int j = 0; j < 4; j++)
                        Oacc[i][j] += a4[i][u] * bb[j];
            }
        }
    }

    // Full row sums: reduce over the 16 tx lanes sharing each query row
    #pragma unroll
    for (int i = 0; i < 8; i++) {
        #pragma unroll
        for (int off = 1; off < 16; off <<= 1)
            lsum[i] += __shfl_xor_sync(0xffffffffu, lsum[i], off);
    }

    // Write in the reference's scrambled layout:
    // e = h*64 + d  ->  g_att[b][(e>>1)][ (e&1)*512 + s ]
    float* ab = g_att + (size_t)b*SEQ*HID;
    #pragma unroll
    for (int i = 0; i < 8; i++) {
        float inv = 1.0f / lsum[i];
        int s = s0 + r[i];
        #pragma unroll
        for (int j = 0; j < 4; j++) {
            int dv = (j < 2) ? (tx*2 + j) : (32 + tx*2 + (j-2));
            int e  = h*HD + dv;
            ab[(size_t)(e >> 1)*HID + (e & 1)*SEQ + s] = Oacc[i][j] * inv;
        }
    }
}

// ---------------------------------------------------------------------------
extern "C" void kernel_launch(void* const* d_in, const int* in_sizes, int n_in,
                              void* d_out, int out_size)
{
    const float* x  = (const float*)d_in[0];
    const float* Wq = (const float*)d_in[1];
    const float* bq = (const float*)d_in[2];
    const float* Wk = (const float*)d_in[3];
    const float* bk = (const float*)d_in[4];
    const float* Wv = (const float*)d_in[5];
    const float* bv = (const float*)d_in[6];
    const float* Wo = (const float*)d_in[7];
    const float* bo = (const float*)d_in[8];
    float* out = (float*)d_out;

    cudaFuncSetAttribute(attn_kernel,
                         cudaFuncAttributeMaxDynamicSharedMemorySize, ATTN_SMEM);

    dim3 gq(HID/128, ROWS/128, 3);     // fused QKV
    qkv_kernel<<<gq, 256>>>(x, Wq, bq, Wk, bk, Wv, bv);

    attn_kernel<<<128, 256, ATTN_SMEM>>>();

    dim3 go(HID/128, ROWS/128);
    oproj_kernel<<<go, 256>>>(Wo, bo, out);
}

// round 2
// speedup vs baseline: 2.0676x; 2.0676x over previous
#include <cuda_runtime.h>

#define HID 1024
#define SEQ 512
#define BATCH 2
#define NH 16
#define HD 64
#define ROWS (BATCH*SEQ)
#define NKEY (SEQ*NH)   // 8192 keys per batch
#define NTILES (NKEY/64)

// Scratch (device globals: no allocations allowed)
__device__ float g_q[ROWS*HID];
__device__ float g_k[ROWS*HID];   // tf32-rounded at producer
__device__ float g_v[ROWS*HID];   // tf32-rounded at producer
__device__ float g_att[ROWS*HID]; // scrambled attention output

// ---------------------------------------------------------------------------
// helpers
// ---------------------------------------------------------------------------
__device__ __forceinline__ float tf32_rna(float x){
    unsigned u; asm("cvt.rna.tf32.f32 %0, %1;" : "=r"(u) : "f"(x));
    return __uint_as_float(u);
}
__device__ __forceinline__ float tf32_trunc(float x){
    return __uint_as_float(__float_as_uint(x) & 0xffffe000u);
}
__device__ __forceinline__ void mma8(float* c, const unsigned* a, unsigned b0, unsigned b1){
    asm volatile("mma.sync.aligned.m16n8k8.row.col.f32.tf32.tf32.f32 "
                 "{%0,%1,%2,%3},{%4,%5,%6,%7},{%8,%9},{%0,%1,%2,%3};"
                 : "+f"(c[0]),"+f"(c[1]),"+f"(c[2]),"+f"(c[3])
                 : "r"(a[0]),"r"(a[1]),"r"(a[2]),"r"(a[3]),"r"(b0),"r"(b1));
}
__device__ __forceinline__ void cp16(float* dst, const float* src){
    unsigned d = (unsigned)__cvta_generic_to_shared(dst);
    asm volatile("cp.async.cg.shared.global [%0], [%1], 16;" :: "r"(d), "l"(src));
}
__device__ __forceinline__ unsigned fbits(float x){ return __float_as_uint(x); }

// ---------------------------------------------------------------------------
// SGEMM: C[1024,1024] = A @ W + bias  (fp32 SIMT, from R1; optional tf32 round)
// ---------------------------------------------------------------------------
__device__ __forceinline__ void gemm_body(const float* __restrict__ A,
                                          const float* __restrict__ W,
                                          const float* __restrict__ bias,
                                          float* __restrict__ C, int round_out)
{
    __shared__ float As[16*128];
    __shared__ float Bs[16*128];

    const int tid = threadIdx.x;
    const int tx = tid & 15, ty = tid >> 4;
    const int m0 = blockIdx.y * 128, n0 = blockIdx.x * 128;

    float acc[8][8];
    #pragma unroll
    for (int i = 0; i < 8; i++)
        #pragma unroll
        for (int j = 0; j < 8; j++) acc[i][j] = 0.f;

    for (int k0 = 0; k0 < HID; k0 += 16) {
        #pragma unroll
        for (int l = 0; l < 2; l++) {
            int i = tid + l*256;
            int ar = i >> 2, ac = (i & 3) << 2;
            float4 va = *(const float4*)(A + (size_t)(m0+ar)*HID + k0 + ac);
            int col = ar ^ ((i & 3) << 2);
            As[(ac+0)*128 + col] = va.x;
            As[(ac+1)*128 + col] = va.y;
            As[(ac+2)*128 + col] = va.z;
            As[(ac+3)*128 + col] = va.w;
            int br = i >> 5, bc = (i & 31) << 2;
            *(float4*)(Bs + br*128 + bc) =
                *(const float4*)(W + (size_t)(k0+br)*HID + n0 + bc);
        }
        __syncthreads();
        #pragma unroll
        for (int kk = 0; kk < 16; kk++) {
            int sw = ((kk >> 2) & 7) << 2;
            float a[8], b[8];
            *(float4*)(a)   = *(const float4*)(As + kk*128 + ((ty*4) ^ sw));
            *(float4*)(a+4) = *(const float4*)(As + kk*128 + ((64 + ty*4) ^ sw));
            *(float4*)(b)   = *(const float4*)(Bs + kk*128 + tx*4);
            *(float4*)(b+4) = *(const float4*)(Bs + kk*128 + 64 + tx*4);
            #pragma unroll
            for (int i = 0; i < 8; i++)
                #pragma unroll
                for (int j = 0; j < 8; j++)
                    acc[i][j] += a[i] * b[j];
        }
        __syncthreads();
    }

    #pragma unroll
    for (int i = 0; i < 8; i++) {
        int m = m0 + ((i < 4) ? (ty*4 + i) : (64 + ty*4 + (i-4)));
        float4 bia0 = *(const float4*)(bias + n0 + tx*4);
        float4 bia1 = *(const float4*)(bias + n0 + 64 + tx*4);
        float o[8];
        o[0]=acc[i][0]+bia0.x; o[1]=acc[i][1]+bia0.y;
        o[2]=acc[i][2]+bia0.z; o[3]=acc[i][3]+bia0.w;
        o[4]=acc[i][4]+bia1.x; o[5]=acc[i][5]+bia1.y;
        o[6]=acc[i][6]+bia1.z; o[7]=acc[i][7]+bia1.w;
        if (round_out) {
            #pragma unroll
            for (int j = 0; j < 8; j++) o[j] = tf32_rna(o[j]);
        }
        *(float4*)(C + (size_t)m*HID + n0 + tx*4)      = make_float4(o[0],o[1],o[2],o[3]);
        *(float4*)(C + (size_t)m*HID + n0 + 64 + tx*4) = make_float4(o[4],o[5],o[6],o[7]);
    }
}

__global__ __launch_bounds__(256)
void qkv_kernel(const float* __restrict__ x,
                const float* __restrict__ Wq, const float* __restrict__ bq,
                const float* __restrict__ Wk, const float* __restrict__ bk,
                const float* __restrict__ Wv, const float* __restrict__ bv)
{
    int z = blockIdx.z;
    const float* W    = (z == 0) ? Wq : (z == 1) ? Wk : Wv;
    const float* bias = (z == 0) ? bq : (z == 1) ? bk : bv;
    float* C          = (z == 0) ? g_q : (z == 1) ? g_k : g_v;
    gemm_body(x, W, bias, C, z != 0);   // round K and V to tf32 at producer
}

__global__ __launch_bounds__(256)
void oproj_kernel(const float* __restrict__ Wo, const float* __restrict__ bo,
                  float* __restrict__ out)
{
    gemm_body(g_att, Wo, bo, out, 0);
}

// ---------------------------------------------------------------------------
// Flash attention with tf32 mma.sync (m16n8k8), no-max softmax.
// 128 blocks = B(2) x H(16) x Qtiles(4 of 128), 256 threads = 8 warps.
// Warp w owns query rows [16w, 16w+16). Q fragments register-resident.
// K tiles of 64 keys, cp.async double-buffered.
// smem strides: Ks 68, Vs 72, Ps 68 (all fragment LDS bank-conflict-free).
// ---------------------------------------------------------------------------
#define KST 68
#define VST 72
#define PST 68
#define KS_OFF0 0
#define KS_OFF1 (64*KST)
#define VS_OFF0 (2*64*KST)
#define VS_OFF1 (2*64*KST + 64*VST)
#define PS_OFF  (2*64*KST + 2*64*VST)
#define ATTN_SMEM ((2*64*KST + 2*64*VST + 128*PST) * 4)

__global__ __launch_bounds__(256)
void attn_kernel()
{
    extern __shared__ float sm[];
    float* Ksb[2] = { sm + KS_OFF0, sm + KS_OFF1 };
    float* Vsb[2] = { sm + VS_OFF0, sm + VS_OFF1 };
    float* Ps     = sm + PS_OFF;

    const int tid  = threadIdx.x;
    const int lane = tid & 31, w = tid >> 5;
    const int g = lane >> 2, q = lane & 3;
    const int bx = blockIdx.x;
    const int b  = bx >> 6;
    const int h  = (bx >> 2) & 15;
    const int s0 = (bx & 3) << 7;

    const float* qb = g_q + (size_t)(b*SEQ + s0)*HID + h*HD;
    const float* kb = g_k + (size_t)b*SEQ*HID;   // [8192, 64] contiguous view
    const float* vb = g_v + (size_t)b*SEQ*HID;

    // --- prefetch K/V tile 0 ---
    {
        #pragma unroll
        for (int l = 0; l < 4; l++) {
            int idx = tid + 256*l;
            int key = idx >> 4, d0 = (idx & 15) << 2;
            cp16(Ksb[0] + key*KST + d0, kb + key*HD + d0);
            cp16(Vsb[0] + key*VST + d0, vb + key*HD + d0);
        }
        asm volatile("cp.async.commit_group;");
    }

    // --- stage Q (scaled + tf32-rounded) into Ps region, then grab fragments ---
    #pragma unroll
    for (int l = 0; l < 8; l++) {
        int idx = tid + 256*l;
        int r = idx >> 4, d0 = (idx & 15) << 2;
        float4 v = *(const float4*)(qb + (size_t)r*HID + d0);
        float* dst = Ps + r*PST + d0;
        dst[0] = tf32_rna(v.x * 0.125f);
        dst[1] = tf32_rna(v.y * 0.125f);
        dst[2] = tf32_rna(v.z * 0.125f);
        dst[3] = tf32_rna(v.w * 0.125f);
    }
    __syncthreads();

    unsigned qf[8][4];
    {
        const float* q0 = Ps + (16*w + g)*PST;
        const float* q1 = Ps + (16*w + 8 + g)*PST;
        #pragma unroll
        for (int kk = 0; kk < 8; kk++) {
            qf[kk][0] = fbits(q0[8*kk + q]);
            qf[kk][1] = fbits(q1[8*kk + q]);
            qf[kk][2] = fbits(q0[8*kk + q + 4]);
            qf[kk][3] = fbits(q1[8*kk + q + 4]);
        }
    }

    float Oacc[8][4];
    #pragma unroll
    for (int nt = 0; nt < 8; nt++)
        #pragma unroll
        for (int j = 0; j < 4; j++) Oacc[nt][j] = 0.f;
    float lsum0 = 0.f, lsum1 = 0.f;

    float* Prow0 = Ps + (16*w + g)*PST;
    float* Prow1 = Ps + (16*w + 8 + g)*PST;

    for (int jt = 0; jt < NTILES; jt++) {
        int cur = jt & 1;
        // prefetch next tile into other buffer
        if (jt + 1 < NTILES) {
            const float* kp = kb + (size_t)(jt+1)*64*HD;
            const float* vp = vb + (size_t)(jt+1)*64*HD;
            float* kd = Ksb[cur ^ 1];
            float* vd = Vsb[cur ^ 1];
            #pragma unroll
            for (int l = 0; l < 4; l++) {
                int idx = tid + 256*l;
                int key = idx >> 4, d0 = (idx & 15) << 2;
                cp16(kd + key*KST + d0, kp + key*HD + d0);
                cp16(vd + key*VST + d0, vp + key*HD + d0);
            }
            asm volatile("cp.async.commit_group;");
            asm volatile("cp.async.wait_group 1;");
        } else {
            asm volatile("cp.async.wait_group 0;");
        }
        __syncthreads();

        const float* K_ = Ksb[cur];
        const float* V_ = Vsb[cur];

        // ---- S = Q @ K^T  (warp: 16 rows x 64 keys) ----
        float sacc[8][4];
        #pragma unroll
        for (int nt = 0; nt < 8; nt++)
            #pragma unroll
            for (int j = 0; j < 4; j++) sacc[nt][j] = 0.f;

        #pragma unroll
        for (int kk = 0; kk < 8; kk++) {
            #pragma unroll
            for (int nt = 0; nt < 8; nt++) {
                const float* kp = K_ + (8*nt + g)*KST + 8*kk + q;
                unsigned b0 = fbits(kp[0]);
                unsigned b1 = fbits(kp[4]);
                mma8(sacc[nt], qf[kk], b0, b1);
            }
        }

        // ---- P = exp(S), tf32-truncate, row sums, stage to smem ----
        #pragma unroll
        for (int nt = 0; nt < 8; nt++) {
            float p0 = tf32_trunc(__expf(sacc[nt][0]));
            float p1 = tf32_trunc(__expf(sacc[nt][1]));
            float p2 = tf32_trunc(__expf(sacc[nt][2]));
            float p3 = tf32_trunc(__expf(sacc[nt][3]));
            lsum0 += p0 + p1;
            lsum1 += p2 + p3;
            *(float2*)(Prow0 + 8*nt + 2*q) = make_float2(p0, p1);
            *(float2*)(Prow1 + 8*nt + 2*q) = make_float2(p2, p3);
        }
        __syncwarp();   // P rows are warp-private: warp sync suffices

        // ---- O += P @ V ----
        #pragma unroll
        for (int kk = 0; kk < 8; kk++) {
            unsigned pa[4];
            pa[0] = fbits(Prow0[8*kk + q]);
            pa[1] = fbits(Prow1[8*kk + q]);
            pa[2] = fbits(Prow0[8*kk + q + 4]);
            pa[3] = fbits(Prow1[8*kk + q + 4]);
            #pragma unroll
            for (int nt = 0; nt < 8; nt++) {
                unsigned b0 = fbits(V_[(8*kk + q    )*VST + 8*nt + g]);
                unsigned b1 = fbits(V_[(8*kk + q + 4)*VST + 8*nt + g]);
                mma8(Oacc[nt], pa, b0, b1);
            }
        }
        __syncthreads();   // all reads of buf[cur] done before next prefetch writes it
    }

    // ---- finalize row sums (reduce across the 4 lanes sharing each row) ----
    lsum0 += __shfl_xor_sync(0xffffffffu, lsum0, 1);
    lsum0 += __shfl_xor_sync(0xffffffffu, lsum0, 2);
    lsum1 += __shfl_xor_sync(0xffffffffu, lsum1, 1);
    lsum1 += __shfl_xor_sync(0xffffffffu, lsum1, 2);
    float inv0 = 1.0f / lsum0;
    float inv1 = 1.0f / lsum1;

    // ---- write scrambled output: e=h*64+d -> g_att[b][(e>>1)][(e&1)*512 + s] ----
    float* ab = g_att + (size_t)b*SEQ*HID;
    int srow0 = s0 + 16*w + g;
    int srow1 = srow0 + 8;
    #pragma unroll
    for (int nt = 0; nt < 8; nt++) {
        int dv = 8*nt + 2*q;
        int e0 = h*HD + dv;
        int e1 = e0 + 1;
        ab[(size_t)(e0 >> 1)*HID + (e0 & 1)*SEQ + srow0] = Oacc[nt][0] * inv0;
        ab[(size_t)(e1 >> 1)*HID + (e1 & 1)*SEQ + srow0] = Oacc[nt][1] * inv0;
        ab[(size_t)(e0 >> 1)*HID + (e0 & 1)*SEQ + srow1] = Oacc[nt][2] * inv1;
        ab[(size_t)(e1 >> 1)*HID + (e1 & 1)*SEQ + srow1] = Oacc[nt][3] * inv1;
    }
}

// ---------------------------------------------------------------------------
extern "C" void kernel_launch(void* const* d_in, const int* in_sizes, int n_in,
                              void* d_out, int out_size)
{
    const float* x  = (const float*)d_in[0];
    const float* Wq = (const float*)d_in[1];
    const float* bq = (const float*)d_in[2];
    const float* Wk = (const float*)d_in[3];
    const float* bk = (const float*)d_in[4];
    const float* Wv = (const float*)d_in[5];
    const float* bv = (const float*)d_in[6];
    const float* Wo = (const float*)d_in[7];
    const float* bo = (const float*)d_in[8];
    float* out = (float*)d_out;

    cudaFuncSetAttribute(attn_kernel,
                         cudaFuncAttributeMaxDynamicSharedMemorySize, ATTN_SMEM);

    dim3 gq(HID/128, ROWS/128, 3);
    qkv_kernel<<<gq, 256>>>(x, Wq, bq, Wk, bk, Wv, bv);

    attn_kernel<<<128, 256, ATTN_SMEM>>>();

    dim3 go(HID/128, ROWS/128);
    oproj_kernel<<<go, 256>>>(Wo, bo, out);
}

// round 4
// speedup vs baseline: 3.1136x; 1.5059x over previous
#include <cuda_runtime.h>
#include <cstdint>

#define HID 1024
#define SEQ 512
#define BATCH 2
#define NH 16
#define HD 64
#define ROWS (BATCH*SEQ)
#define NKEY (SEQ*NH)
#define NT 128

// Scratch (device globals)
__device__ float g_q[ROWS*HID];
__device__ float g_k[ROWS*HID];
__device__ float g_v[ROWS*HID];
__device__ float g_att[ROWS*HID];
__device__ float g_xr[ROWS*HID];
__device__ float g_wr[4*HID*HID];   // Wq, Wk, Wv, Wo (tf32-rounded)

// ---------------------------------------------------------------------------
__device__ __forceinline__ float tf32_rna(float x){
    unsigned u; asm("cvt.rna.tf32.f32 %0, %1;" : "=r"(u) : "f"(x));
    return __uint_as_float(u);
}
__device__ __forceinline__ float tf32_trunc(float x){
    return __uint_as_float(__float_as_uint(x) & 0xffffe000u);
}
__device__ __forceinline__ unsigned fbits(float x){ return __float_as_uint(x); }
__device__ __forceinline__ void mma8(float* c, const unsigned* a, unsigned b0, unsigned b1){
    asm volatile("mma.sync.aligned.m16n8k8.row.col.f32.tf32.tf32.f32 "
                 "{%0,%1,%2,%3},{%4,%5,%6,%7},{%8,%9},{%0,%1,%2,%3};"
                 : "+f"(c[0]),"+f"(c[1]),"+f"(c[2]),"+f"(c[3])
                 : "r"(a[0]),"r"(a[1]),"r"(a[2]),"r"(a[3]),"r"(b0),"r"(b1));
}
__device__ __forceinline__ void cp16(uint32_t dst, const float* src){
    asm volatile("cp.async.cg.shared.global [%0], [%1], 16;" :: "r"(dst), "l"(src));
}
__device__ __forceinline__ uint32_t smem_u32(const void* p){
    uint32_t a;
    asm("{ .reg .u64 t; cvta.to.shared.u64 t, %1; cvt.u32.u64 %0, t; }" : "=r"(a) : "l"(p));
    return a;
}
#define CP_COMMIT() asm volatile("cp.async.commit_group;")
#define CP_WAIT0()  asm volatile("cp.async.wait_group 0;")

// ---------------------------------------------------------------------------
// Pre-round x + 4 weight matrices to tf32 (RNA).  grid (1024,1,5), 256 thr.
// ---------------------------------------------------------------------------
__global__ __launch_bounds__(256)
void round_kernel(const float* __restrict__ x,  const float* __restrict__ Wq,
                  const float* __restrict__ Wk, const float* __restrict__ Wv,
                  const float* __restrict__ Wo)
{
    int z = blockIdx.z;
    const float* src = (z==0)?x:(z==1)?Wq:(z==2)?Wk:(z==3)?Wv:Wo;
    float* dst = (z==0)?g_xr:(g_wr + (size_t)(z-1)*HID*HID);
    size_t i = ((size_t)blockIdx.x*256 + threadIdx.x)*4;
    float4 v = *(const float4*)(src + i);
    *(float4*)(dst + i) = make_float4(tf32_rna(v.x), tf32_rna(v.y),
                                      tf32_rna(v.z), tf32_rna(v.w));
}

// ---------------------------------------------------------------------------
// tf32 mma projection GEMM: C[1024,1024] = A @ W + bias
// 512 threads, 16 warps (4x4), warp tile 32x32, k-tile 32, double-buffered.
// ---------------------------------------------------------------------------
#define GA_ST 36
#define GB_ST 136
#define GK 32
#define GEMM_SMEM ((2*128*GA_ST + 2*GK*GB_ST)*4)

__device__ __forceinline__ void gemm_tc_body(const float* __restrict__ A,
                                             const float* __restrict__ W,
                                             const float* __restrict__ bias,
                                             float* __restrict__ C, int round_out)
{
    extern __shared__ float sm[];
    const uint32_t sb = smem_u32(sm);
    float* Asb[2] = { sm, sm + 128*GA_ST };
    float* Bsb[2] = { sm + 2*128*GA_ST, sm + 2*128*GA_ST + GK*GB_ST };
    const uint32_t au[2] = { sb, sb + 128*GA_ST*4 };
    const uint32_t bu[2] = { sb + 2*128*GA_ST*4u, sb + (2*128*GA_ST + GK*GB_ST)*4u };

    const int tid = threadIdx.x;
    const int w = tid >> 5, lane = tid & 31;
    const int g = lane >> 2, q = lane & 3;
    const int wr = w >> 2, wc = w & 3;
    const int m0 = blockIdx.y*128, n0 = blockIdx.x*128;

    float cacc[2][4][4];
    #pragma unroll
    for (int mf = 0; mf < 2; mf++)
        #pragma unroll
        for (int nf = 0; nf < 4; nf++)
            #pragma unroll
            for (int j = 0; j < 4; j++) cacc[mf][nf][j] = 0.f;

    // prefetch tile 0
    {
        #pragma unroll
        for (int t = 0; t < 2; t++) {
            int c = tid + 512*t;
            int ar = c >> 3, ac = (c & 7) << 2;
            cp16(au[0] + (ar*GA_ST + ac)*4u, A + (size_t)(m0+ar)*HID + ac);
            int br = c >> 5, bc = (c & 31) << 2;
            cp16(bu[0] + (br*GB_ST + bc)*4u, W + (size_t)br*HID + n0 + bc);
        }
        CP_COMMIT();
    }

    for (int kt = 0; kt < HID/GK; kt++) {
        CP_WAIT0();
        __syncthreads();
        if (kt + 1 < HID/GK) {
            int nb = (kt+1) & 1, k0 = (kt+1)*GK;
            #pragma unroll
            for (int t = 0; t < 2; t++) {
                int c = tid + 512*t;
                int ar = c >> 3, ac = (c & 7) << 2;
                cp16(au[nb] + (ar*GA_ST + ac)*4u, A + (size_t)(m0+ar)*HID + k0 + ac);
                int br = c >> 5, bc = (c & 31) << 2;
                cp16(bu[nb] + (br*GB_ST + bc)*4u, W + (size_t)(k0+br)*HID + n0 + bc);
            }
            CP_COMMIT();
        }
        const float* Ab = Asb[kt & 1];
        const float* Bb = Bsb[kt & 1];

        #pragma unroll
        for (int kk = 0; kk < 4; kk++) {
            unsigned af[2][4], bf[4][2];
            #pragma unroll
            for (int mf = 0; mf < 2; mf++) {
                int r0 = 32*wr + 16*mf;
                af[mf][0] = fbits(Ab[(r0 + g    )*GA_ST + 8*kk + q    ]);
                af[mf][1] = fbits(Ab[(r0 + 8 + g)*GA_ST + 8*kk + q    ]);
                af[mf][2] = fbits(Ab[(r0 + g    )*GA_ST + 8*kk + q + 4]);
                af[mf][3] = fbits(Ab[(r0 + 8 + g)*GA_ST + 8*kk + q + 4]);
            }
            #pragma unroll
            for (int nf = 0; nf < 4; nf++) {
                int col = 32*wc + 8*nf + g;
                bf[nf][0] = fbits(Bb[(8*kk + q    )*GB_ST + col]);
                bf[nf][1] = fbits(Bb[(8*kk + q + 4)*GB_ST + col]);
            }
            #pragma unroll
            for (int mf = 0; mf < 2; mf++)
                #pragma unroll
                for (int nf = 0; nf < 4; nf++)
                    mma8(cacc[mf][nf], af[mf], bf[nf][0], bf[nf][1]);
        }
    }

    #pragma unroll
    for (int mf = 0; mf < 2; mf++) {
        #pragma unroll
        for (int rr = 0; rr < 2; rr++) {
            int row = m0 + 32*wr + 16*mf + g + rr*8;
            #pragma unroll
            for (int nf = 0; nf < 4; nf++) {
                int col = n0 + 32*wc + 8*nf + 2*q;
                float o0 = cacc[mf][nf][rr*2]   + __ldg(bias + col);
                float o1 = cacc[mf][nf][rr*2+1] + __ldg(bias + col + 1);
                if (round_out) { o0 = tf32_rna(o0); o1 = tf32_rna(o1); }
                *(float2*)(C + (size_t)row*HID + col) = make_float2(o0, o1);
            }
        }
    }
}

__global__ __launch_bounds__(512)
void qkv_kernel(const float* __restrict__ bq, const float* __restrict__ bk,
                const float* __restrict__ bv)
{
    int z = blockIdx.z;
    const float* W    = g_wr + (size_t)z*HID*HID;
    const float* bias = (z == 0) ? bq : (z == 1) ? bk : bv;
    float* C          = (z == 0) ? g_q : (z == 1) ? g_k : g_v;
    gemm_tc_body(g_xr, W, bias, C, 1);
}

__global__ __launch_bounds__(512)
void oproj_kernel(const float* __restrict__ bo, float* __restrict__ out)
{
    gemm_tc_body(g_att, g_wr + (size_t)3*HID*HID, bo, out, 0);
}

// ---------------------------------------------------------------------------
// tf32 mma flash attention, no-max softmax, P kept in registers.
// 128 CTAs = B(2) x H(16) x Qtiles(4x128). 512 threads = 16 warps.
// Warp: rg = w&7 (16 rows), kh = w>>3 (32-key half). V rows key-permuted
// (j -> 2j / 2j+1 within 8-groups) so exp'd QK^T accumulators serve directly
// as PV A-fragments.
// ---------------------------------------------------------------------------
#define KST 68
#define VST 72
#define AK0 0
#define AK1 (64*KST)
#define AV0 (2*64*KST)
#define AV1 (2*64*KST + 64*VST)
#define ALS (2*64*KST + 2*64*VST)          // 17920 floats
#define OSM_ST 66
#define ATTN_SMEM ((ALS + 256)*4)

__global__ __launch_bounds__(512)
void attn_kernel()
{
    extern __shared__ float sm[];
    const uint32_t sb = smem_u32(sm);
    const uint32_t ku[2] = { sb + AK0*4u, sb + AK1*4u };
    const uint32_t vu[2] = { sb + AV0*4u, sb + AV1*4u };
    float* Ksb[2] = { sm + AK0, sm + AK1 };
    float* Vsb[2] = { sm + AV0, sm + AV1 };
    float* lsumS  = sm + ALS;               // [2][128]
    float* Osm    = sm;                     // epilogue reuse of K/V region

    const int tid = threadIdx.x;
    const int w = tid >> 5, lane = tid & 31;
    const int g = lane >> 2, q = lane & 3;
    const int rg = w & 7, kh = w >> 3;
    const int bx = blockIdx.x;
    const int b  = bx >> 6;
    const int h  = (bx >> 2) & 15;
    const int s0 = (bx & 3) << 7;

    const float* kb0 = g_k + (size_t)b*SEQ*HID;   // [8192,64] view
    const float* vb0 = g_v + (size_t)b*SEQ*HID;

    // prefetch tile 0 (V with in-group key permutation)
    {
        #pragma unroll
        for (int t = 0; t < 2; t++) {
            int c = tid + 512*t;
            int r = c >> 4, col = (c & 15) << 2;
            cp16(ku[0] + (r*KST + col)*4u, kb0 + (size_t)r*HD + col);
            int pr = (r & 56) | ((r & 3) << 1) | ((r >> 2) & 1);
            cp16(vu[0] + (r*VST + col)*4u, vb0 + (size_t)pr*HD + col);
        }
        CP_COMMIT();
    }

    // Q fragments (producer already tf32-rounded; *0.125 is exact)
    unsigned qf[8][4];
    {
        const float* qb = g_q + (size_t)(b*SEQ + s0)*HID + h*HD;
        #pragma unroll
        for (int kk = 0; kk < 8; kk++) {
            qf[kk][0] = fbits(qb[(size_t)(16*rg + g    )*HID + 8*kk + q    ] * 0.125f);
            qf[kk][1] = fbits(qb[(size_t)(16*rg + 8 + g)*HID + 8*kk + q    ] * 0.125f);
            qf[kk][2] = fbits(qb[(size_t)(16*rg + g    )*HID + 8*kk + q + 4] * 0.125f);
            qf[kk][3] = fbits(qb[(size_t)(16*rg + 8 + g)*HID + 8*kk + q + 4] * 0.125f);
        }
    }

    float Oacc[8][4];
    #pragma unroll
    for (int nt = 0; nt < 8; nt++)
        #pragma unroll
        for (int j = 0; j < 4; j++) Oacc[nt][j] = 0.f;
    float lr0 = 0.f, lr1 = 0.f;

    for (int jt = 0; jt < NT; jt++) {
        CP_WAIT0();
        __syncthreads();
        if (jt + 1 < NT) {
            int nb = (jt+1) & 1;
            const float* kp = kb0 + (size_t)(jt+1)*64*HD;
            const float* vp = vb0 + (size_t)(jt+1)*64*HD;
            #pragma unroll
            for (int t = 0; t < 2; t++) {
                int c = tid + 512*t;
                int r = c >> 4, col = (c & 15) << 2;
                cp16(ku[nb] + (r*KST + col)*4u, kp + (size_t)r*HD + col);
                int pr = (r & 56) | ((r & 3) << 1) | ((r >> 2) & 1);
                cp16(vu[nb] + (r*VST + col)*4u, vp + (size_t)pr*HD + col);
            }
            CP_COMMIT();
        }
        const float* K_ = Ksb[jt & 1];
        const float* V_ = Vsb[jt & 1];

        // ---- S = Q @ K^T : 16 rows x 32 keys ----
        float p[4][4];
        #pragma unroll
        for (int nt = 0; nt < 4; nt++)
            #pragma unroll
            for (int j = 0; j < 4; j++) p[nt][j] = 0.f;

        #pragma unroll
        for (int kk = 0; kk < 8; kk++) {
            #pragma unroll
            for (int nt = 0; nt < 4; nt++) {
                const float* kr = K_ + (32*kh + 8*nt + g)*KST + 8*kk + q;
                mma8(p[nt], qf[kk], fbits(kr[0]), fbits(kr[4]));
            }
        }

        // ---- exp + partial row sums ----
        #pragma unroll
        for (int nt = 0; nt < 4; nt++) {
            p[nt][0] = tf32_trunc(__expf(p[nt][0]));
            p[nt][1] = tf32_trunc(__expf(p[nt][1]));
            p[nt][2] = tf32_trunc(__expf(p[nt][2]));
            p[nt][3] = tf32_trunc(__expf(p[nt][3]));
            lr0 += p[nt][0] + p[nt][1];
            lr1 += p[nt][2] + p[nt][3];
        }

        // ---- O += P @ V (accumulators reused as A-frags via V permutation) ----
        #pragma unroll
        for (int kg = 0; kg < 4; kg++) {
            unsigned pa[4] = { fbits(p[kg][0]), fbits(p[kg][2]),
                               fbits(p[kg][1]), fbits(p[kg][3]) };
            #pragma unroll
            for (int nt = 0; nt < 8; nt++) {
                unsigned b0 = fbits(V_[(32*kh + 8*kg + q    )*VST + 8*nt + g]);
                unsigned b1 = fbits(V_[(32*kh + 8*kg + q + 4)*VST + 8*nt + g]);
                mma8(Oacc[nt], pa, b0, b1);
            }
        }
    }

    // ---- reduce lsum over the 4 q-lanes; publish per key-half ----
    lr0 += __shfl_xor_sync(0xffffffffu, lr0, 1);
    lr0 += __shfl_xor_sync(0xffffffffu, lr0, 2);
    lr1 += __shfl_xor_sync(0xffffffffu, lr1, 1);
    lr1 += __shfl_xor_sync(0xffffffffu, lr1, 2);

    __syncthreads();   // all V reads done before Osm reuse
    if (q == 0) {
        lsumS[kh*128 + 16*rg + g]     = lr0;
        lsumS[kh*128 + 16*rg + 8 + g] = lr1;
    }
    if (kh == 0) {
        #pragma unroll
        for (int nt = 0; nt < 8; nt++) {
            *(float2*)(Osm + (16*rg + g    )*OSM_ST + 8*nt + 2*q) =
                make_float2(Oacc[nt][0], Oacc[nt][1]);
            *(float2*)(Osm + (16*rg + 8 + g)*OSM_ST + 8*nt + 2*q) =
                make_float2(Oacc[nt][2], Oacc[nt][3]);
        }
    }
    __syncthreads();

    if (kh == 1) {
        int row0 = 16*rg + g, row1 = row0 + 8;
        float inv0 = 1.0f / (lsumS[row0] + lsumS[128 + row0]);
        float inv1 = 1.0f / (lsumS[row1] + lsumS[128 + row1]);
        float* ab = g_att + (size_t)b*SEQ*HID;
        int sA = s0 + row0, sB = s0 + row1;
        #pragma unroll
        for (int nt = 0; nt < 8; nt++) {
            float2 h0 = *(float2*)(Osm + row0*OSM_ST + 8*nt + 2*q);
            float2 h1 = *(float2*)(Osm + row1*OSM_ST + 8*nt + 2*q);
            float o0 = (Oacc[nt][0] + h0.x) * inv0;
            float o1 = (Oacc[nt][1] + h0.y) * inv0;
            float o2 = (Oacc[nt][2] + h1.x) * inv1;
            float o3 = (Oacc[nt][3] + h1.y) * inv1;
            int e = h*HD + 8*nt + 2*q;          // even
            size_t base = (size_t)(e >> 1)*HID;
            ab[base + sA]       = tf32_rna(o0);
            ab[base + SEQ + sA] = tf32_rna(o1);
            ab[base + sB]       = tf32_rna(o2);
            ab[base + SEQ + sB] = tf32_rna(o3);
        }
    }
}

// ---------------------------------------------------------------------------
extern "C" void kernel_launch(void* const* d_in, const int* in_sizes, int n_in,
                              void* d_out, int out_size)
{
    const float* x  = (const float*)d_in[0];
    const float* Wq = (const float*)d_in[1];
    const float* bq = (const float*)d_in[2];
    const float* Wk = (const float*)d_in[3];
    const float* bk = (const float*)d_in[4];
    const float* Wv = (const float*)d_in[5];
    const float* bv = (const float*)d_in[6];
    const float* Wo = (const float*)d_in[7];
    const float* bo = (const float*)d_in[8];
    float* out = (float*)d_out;

    cudaFuncSetAttribute(qkv_kernel,
                         cudaFuncAttributeMaxDynamicSharedMemorySize, GEMM_SMEM);
    cudaFuncSetAttribute(oproj_kernel,
                         cudaFuncAttributeMaxDynamicSharedMemorySize, GEMM_SMEM);
    cudaFuncSetAttribute(attn_kernel,
                         cudaFuncAttributeMaxDynamicSharedMemorySize, ATTN_SMEM);

    round_kernel<<<dim3(1024,1,5), 256>>>(x, Wq, Wk, Wv, Wo);

    qkv_kernel<<<dim3(8,8,3), 512, GEMM_SMEM>>>(bq, bk, bv);

    attn_kernel<<<128, 512, ATTN_SMEM>>>();

    oproj_kernel<<<dim3(8,8), 512, GEMM_SMEM>>>(bo, out);
}

// round 5
// speedup vs baseline: 5.9451x; 1.9094x over previous
#include <cuda_runtime.h>
#include <cuda_fp16.h>
#include <cstdint>

#define HID 1024
#define SEQ 512
#define BATCH 2
#define NH 16
#define HD 64
#define ROWS (BATCH*SEQ)
#define NKEY (SEQ*NH)
#define NT 128

// Scratch (device globals)
__device__ __half g_qh[ROWS*HID];            // Q (pre-scaled by 0.125), [b*512+s][h*64+d]
__device__ __half g_kh[ROWS*HID];            // K, [b][j=s*16+h'][d]  (same flat layout)
__device__ __half g_vt[BATCH*HD*NKEY];       // V^T, [b][dd][j]
__device__ __half g_att[ROWS*HID];           // scrambled attention output
__device__ __half g_xh[ROWS*HID];            // x in fp16
__device__ __half g_wh[4*HID*HID];           // W^T in fp16: [z][n][k]

// ---------------------------------------------------------------------------
__device__ __forceinline__ uint32_t h2bits(__half2 h){ return *(uint32_t*)&h; }
__device__ __forceinline__ void mma16(float* c, const uint32_t* a, uint32_t b0, uint32_t b1){
    asm volatile("mma.sync.aligned.m16n8k16.row.col.f32.f16.f16.f32 "
                 "{%0,%1,%2,%3},{%4,%5,%6,%7},{%8,%9},{%0,%1,%2,%3};"
                 : "+f"(c[0]),"+f"(c[1]),"+f"(c[2]),"+f"(c[3])
                 : "r"(a[0]),"r"(a[1]),"r"(a[2]),"r"(a[3]),"r"(b0),"r"(b1));
}
__device__ __forceinline__ void cp16(uint32_t dst, const void* src){
    asm volatile("cp.async.cg.shared.global [%0], [%1], 16;" :: "r"(dst), "l"(src));
}
__device__ __forceinline__ uint32_t smem_u32(const void* p){
    uint32_t a;
    asm("{ .reg .u64 t; cvta.to.shared.u64 t, %1; cvt.u32.u64 %0, t; }" : "=r"(a) : "l"(p));
    return a;
}
#define CP_COMMIT() asm volatile("cp.async.commit_group;")
#define CP_WAIT0()  asm volatile("cp.async.wait_group 0;")

// ---------------------------------------------------------------------------
// x -> fp16 (same layout). grid 1024, 256 thr.
// ---------------------------------------------------------------------------
__global__ __launch_bounds__(256)
void round_x_kernel(const float* __restrict__ x)
{
    size_t i = ((size_t)blockIdx.x*256 + threadIdx.x)*4;
    float4 v = *(const float4*)(x + i);
    __half2 lo = __floats2half2_rn(v.x, v.y);
    __half2 hi = __floats2half2_rn(v.z, v.w);
    *(uint2*)(g_xh + i) = make_uint2(h2bits(lo), h2bits(hi));
}

// ---------------------------------------------------------------------------
// W[k][n] -> W^T fp16 [z][n][k]. grid (16,16,4), 256 thr, 64x64 tiles.
// ---------------------------------------------------------------------------
__global__ __launch_bounds__(256)
void transw_kernel(const float* __restrict__ Wq, const float* __restrict__ Wk,
                   const float* __restrict__ Wv, const float* __restrict__ Wo)
{
    __shared__ float ts[64][65];
    const int z = blockIdx.z;
    const float* W = (z==0)?Wq:(z==1)?Wk:(z==2)?Wv:Wo;
    const int k0 = blockIdx.x*64, n0 = blockIdx.y*64;
    const int tid = threadIdx.x;

    #pragma unroll
    for (int t = 0; t < 4; t++) {
        int idx = tid + 256*t;
        int r = idx >> 4, c4 = (idx & 15) << 2;
        float4 v = *(const float4*)(W + (size_t)(k0+r)*HID + n0 + c4);
        ts[r][c4] = v.x; ts[r][c4+1] = v.y; ts[r][c4+2] = v.z; ts[r][c4+3] = v.w;
    }
    __syncthreads();
    #pragma unroll
    for (int t = 0; t < 4; t++) {
        int idx = tid + 256*t;
        int r = idx >> 4, c4 = (idx & 15) << 2;   // r: n index, c4: k index
        __half2 lo = __floats2half2_rn(ts[c4][r],   ts[c4+1][r]);
        __half2 hi = __floats2half2_rn(ts[c4+2][r], ts[c4+3][r]);
        *(uint2*)(g_wh + (size_t)z*HID*HID + (size_t)(n0+r)*HID + k0 + c4) =
            make_uint2(h2bits(lo), h2bits(hi));
    }
}

// ---------------------------------------------------------------------------
// fp16 mma GEMM: C[1024,1024] = A @ W + bias.  BM=64, BN=128, BK=32.
// 256 thr = 8 warps (2x4), warp tile 32x32, double-buffered cp.async.
// mode: 0=Q(half,*0.125), 1=K(half), 2=V(->g_vt transposed), 3=O(float out)
// ---------------------------------------------------------------------------
#define AST 40
#define BST 40
#define ASZ (64*AST)
#define BSZ (128*BST)
#define GEMM_SMEM ((2*ASZ + 2*BSZ)*2)

__device__ __forceinline__ void gemm_fp16_body(const __half* __restrict__ A,
                                               const __half* __restrict__ Wt,
                                               const float* __restrict__ bias,
                                               int mode, float* __restrict__ outf)
{
    extern __shared__ __align__(16) char smc[];
    __half* sh = (__half*)smc;
    const uint32_t sb = smem_u32(sh);
    __half* Asb[2] = { sh, sh + ASZ };
    __half* Bsb[2] = { sh + 2*ASZ, sh + 2*ASZ + BSZ };
    const uint32_t au[2] = { sb, sb + ASZ*2u };
    const uint32_t bu[2] = { sb + 2u*ASZ*2u, sb + (2u*ASZ + BSZ)*2u };

    const int tid = threadIdx.x;
    const int w = tid >> 5, lane = tid & 31;
    const int g = lane >> 2, q = lane & 3;
    const int wr = w >> 2, wc = w & 3;
    const int m0 = blockIdx.y*64, n0 = blockIdx.x*128;

    float cacc[2][4][4];
    #pragma unroll
    for (int mf = 0; mf < 2; mf++)
        #pragma unroll
        for (int nf = 0; nf < 4; nf++)
            #pragma unroll
            for (int j = 0; j < 4; j++) cacc[mf][nf][j] = 0.f;

    // prefetch k-tile 0
    {
        int ar = tid >> 2, ac = (tid & 3) << 3;
        cp16(au[0] + (ar*AST + ac)*2u, A + (size_t)(m0+ar)*HID + ac);
        #pragma unroll
        for (int t = 0; t < 2; t++) {
            int c = tid + 256*t;
            int br = c >> 2, bc = (c & 3) << 3;
            cp16(bu[0] + (br*BST + bc)*2u, Wt + (size_t)(n0+br)*HID + bc);
        }
        CP_COMMIT();
    }

    for (int kt = 0; kt < HID/32; kt++) {
        CP_WAIT0();
        __syncthreads();
        if (kt + 1 < HID/32) {
            int nb = (kt+1) & 1, k0 = (kt+1)*32;
            int ar = tid >> 2, ac = (tid & 3) << 3;
            cp16(au[nb] + (ar*AST + ac)*2u, A + (size_t)(m0+ar)*HID + k0 + ac);
            #pragma unroll
            for (int t = 0; t < 2; t++) {
                int c = tid + 256*t;
                int br = c >> 2, bc = (c & 3) << 3;
                cp16(bu[nb] + (br*BST + bc)*2u, Wt + (size_t)(n0+br)*HID + k0 + bc);
            }
            CP_COMMIT();
        }
        const __half* Ab = Asb[kt & 1];
        const __half* Bb = Bsb[kt & 1];

        #pragma unroll
        for (int kk = 0; kk < 2; kk++) {
            uint32_t af[2][4], bf[4][2];
            #pragma unroll
            for (int mf = 0; mf < 2; mf++) {
                int r0 = 32*wr + 16*mf;
                af[mf][0] = h2bits(*(const __half2*)(Ab + (r0+g  )*AST + 16*kk + 2*q));
                af[mf][1] = h2bits(*(const __half2*)(Ab + (r0+8+g)*AST + 16*kk + 2*q));
                af[mf][2] = h2bits(*(const __half2*)(Ab + (r0+g  )*AST + 16*kk + 8 + 2*q));
                af[mf][3] = h2bits(*(const __half2*)(Ab + (r0+8+g)*AST + 16*kk + 8 + 2*q));
            }
            #pragma unroll
            for (int nf = 0; nf < 4; nf++) {
                int col = 32*wc + 8*nf + g;
                bf[nf][0] = h2bits(*(const __half2*)(Bb + col*BST + 16*kk + 2*q));
                bf[nf][1] = h2bits(*(const __half2*)(Bb + col*BST + 16*kk + 8 + 2*q));
            }
            #pragma unroll
            for (int mf = 0; mf < 2; mf++)
                #pragma unroll
                for (int nf = 0; nf < 4; nf++)
                    mma16(cacc[mf][nf], af[mf], bf[nf][0], bf[nf][1]);
        }
    }

    #pragma unroll
    for (int mf = 0; mf < 2; mf++) {
        #pragma unroll
        for (int rr = 0; rr < 2; rr++) {
            int row = m0 + 32*wr + 16*mf + 8*rr + g;
            #pragma unroll
            for (int nf = 0; nf < 4; nf++) {
                int col = n0 + 32*wc + 8*nf + 2*q;
                float o0 = cacc[mf][nf][rr*2]   + __ldg(bias + col);
                float o1 = cacc[mf][nf][rr*2+1] + __ldg(bias + col + 1);
                if (mode == 0) {
                    __half2 h = __floats2half2_rn(o0*0.125f, o1*0.125f);
                    *(uint32_t*)(g_qh + (size_t)row*HID + col) = h2bits(h);
                } else if (mode == 1) {
                    __half2 h = __floats2half2_rn(o0, o1);
                    *(uint32_t*)(g_kh + (size_t)row*HID + col) = h2bits(h);
                } else if (mode == 2) {
                    int hh = col >> 6, dd = col & 63;
                    int s = row & 511, bb = row >> 9;
                    __half* dst = g_vt + (size_t)bb*HD*NKEY + s*16 + hh;
                    dst[(size_t)dd*NKEY]     = __float2half_rn(o0);
                    dst[(size_t)(dd+1)*NKEY] = __float2half_rn(o1);
                } else {
                    *(float2*)(outf + (size_t)row*HID + col) = make_float2(o0, o1);
                }
            }
        }
    }
}

__global__ __launch_bounds__(256)
void qkv_kernel(const float* __restrict__ bq, const float* __restrict__ bk,
                const float* __restrict__ bv)
{
    int z = blockIdx.z;
    const float* bias = (z == 0) ? bq : (z == 1) ? bk : bv;
    gemm_fp16_body(g_xh, g_wh + (size_t)z*HID*HID, bias, z, nullptr);
}

__global__ __launch_bounds__(256)
void oproj_kernel(const float* __restrict__ bo, float* __restrict__ out)
{
    gemm_fp16_body(g_att, g_wh + (size_t)3*HID*HID, bo, 3, out);
}

// ---------------------------------------------------------------------------
// fp16 mma flash attention, no-max softmax, P register-native via k=16 frags.
// 128 CTAs = B(2) x H(16) x Qtiles(4x128). 512 thr = 16 warps.
// Warp: rg=w&7 (16 rows), kh=w>>3 (32-key half of each 64-key tile).
// smem: K[2][64][72] + Vt[2][64][72] halves (36864 B) + lsum 256 floats.
// ---------------------------------------------------------------------------
#define KSTH 72
#define KBUF (64*KSTH)
#define OSM_ST 66
#define ATTN_SMEM (4*KBUF*2 + 1024)

__global__ __launch_bounds__(512)
void attn_kernel()
{
    extern __shared__ __align__(16) char smc[];
    __half* sh = (__half*)smc;
    const uint32_t sb = smem_u32(sh);
    __half* Ksb[2] = { sh, sh + KBUF };
    __half* Vsb[2] = { sh + 2*KBUF, sh + 3*KBUF };
    const uint32_t ku[2] = { sb, sb + KBUF*2u };
    const uint32_t vu[2] = { sb + 2u*KBUF*2u, sb + 3u*KBUF*2u };
    float* lsumS = (float*)(smc + 4*KBUF*2);
    float* Osm   = (float*)smc;

    const int tid = threadIdx.x;
    const int w = tid >> 5, lane = tid & 31;
    const int g = lane >> 2, q = lane & 3;
    const int rg = w & 7, kh = w >> 3;
    const int bx = blockIdx.x;
    const int b  = bx >> 6;
    const int h  = (bx >> 2) & 15;
    const int s0 = (bx & 3) << 7;

    const __half* kb0 = g_kh + (size_t)b*SEQ*HID;        // [8192][64]
    const __half* vt0 = g_vt + (size_t)b*HD*NKEY;        // [64][8192]

    const int pr = tid >> 3, pc = (tid & 7) << 3;        // prefetch coords

    // prefetch tile 0
    cp16(ku[0] + (pr*KSTH + pc)*2u, kb0 + (size_t)pr*HD + pc);
    cp16(vu[0] + (pr*KSTH + pc)*2u, vt0 + (size_t)pr*NKEY + pc);
    CP_COMMIT();

    // Q fragments (Q pre-scaled fp16 in gmem)
    uint32_t qf[4][4];
    {
        const __half* qb = g_qh + (size_t)(b*SEQ + s0)*HID + h*HD;
        const __half* q0 = qb + (size_t)(16*rg + g)*HID;
        const __half* q1 = qb + (size_t)(16*rg + 8 + g)*HID;
        #pragma unroll
        for (int kt = 0; kt < 4; kt++) {
            qf[kt][0] = h2bits(*(const __half2*)(q0 + 16*kt + 2*q));
            qf[kt][1] = h2bits(*(const __half2*)(q1 + 16*kt + 2*q));
            qf[kt][2] = h2bits(*(const __half2*)(q0 + 16*kt + 8 + 2*q));
            qf[kt][3] = h2bits(*(const __half2*)(q1 + 16*kt + 8 + 2*q));
        }
    }

    float Oacc[8][4];
    #pragma unroll
    for (int nt = 0; nt < 8; nt++)
        #pragma unroll
        for (int j = 0; j < 4; j++) Oacc[nt][j] = 0.f;
    float lr0 = 0.f, lr1 = 0.f;

    for (int jt = 0; jt < NT; jt++) {
        CP_WAIT0();
        __syncthreads();
        if (jt + 1 < NT) {
            int nb = (jt+1) & 1;
            cp16(ku[nb] + (pr*KSTH + pc)*2u,
                 kb0 + (size_t)(jt+1)*64*HD + (size_t)pr*HD + pc);
            cp16(vu[nb] + (pr*KSTH + pc)*2u,
                 vt0 + (size_t)pr*NKEY + (jt+1)*64 + pc);
            CP_COMMIT();
        }
        const __half* K_ = Ksb[jt & 1];
        const __half* V_ = Vsb[jt & 1];

        // ---- S = Q @ K^T : 16 rows x 32 keys (4 chunks of 8) ----
        float p[4][4];
        #pragma unroll
        for (int c = 0; c < 4; c++)
            #pragma unroll
            for (int j = 0; j < 4; j++) p[c][j] = 0.f;

        #pragma unroll
        for (int kt = 0; kt < 4; kt++) {
            #pragma unroll
            for (int c = 0; c < 4; c++) {
                const __half* kr = K_ + (32*kh + 8*c + g)*KSTH + 16*kt;
                uint32_t b0 = h2bits(*(const __half2*)(kr + 2*q));
                uint32_t b1 = h2bits(*(const __half2*)(kr + 8 + 2*q));
                mma16(p[c], qf[kt], b0, b1);
            }
        }

        // ---- exp; pack to fp16; sums over the rounded values ----
        uint32_t pk[4][2];
        #pragma unroll
        for (int c = 0; c < 4; c++) {
            __half2 h0 = __floats2half2_rn(__expf(p[c][0]), __expf(p[c][1]));
            __half2 h1 = __floats2half2_rn(__expf(p[c][2]), __expf(p[c][3]));
            pk[c][0] = h2bits(h0);
            pk[c][1] = h2bits(h1);
            float2 f0 = __half22float2(h0);
            float2 f1 = __half22float2(h1);
            lr0 += f0.x + f0.y;
            lr1 += f1.x + f1.y;
        }

        // ---- O += P @ V : A-frags straight from pk ----
        #pragma unroll
        for (int u = 0; u < 2; u++) {
            uint32_t pa[4] = { pk[2*u][0], pk[2*u][1], pk[2*u+1][0], pk[2*u+1][1] };
            #pragma unroll
            for (int nt = 0; nt < 8; nt++) {
                const __half* vr = V_ + (8*nt + g)*KSTH + 32*kh + 16*u;
                uint32_t b0 = h2bits(*(const __half2*)(vr + 2*q));
                uint32_t b1 = h2bits(*(const __half2*)(vr + 8 + 2*q));
                mma16(Oacc[nt], pa, b0, b1);
            }
        }
    }

    // ---- reduce lsum over q lanes; combine key-halves via smem ----
    lr0 += __shfl_xor_sync(0xffffffffu, lr0, 1);
    lr0 += __shfl_xor_sync(0xffffffffu, lr0, 2);
    lr1 += __shfl_xor_sync(0xffffffffu, lr1, 1);
    lr1 += __shfl_xor_sync(0xffffffffu, lr1, 2);

    __syncthreads();   // all K/V reads done before Osm reuse
    if (q == 0) {
        lsumS[kh*128 + 16*rg + g]     = lr0;
        lsumS[kh*128 + 16*rg + 8 + g] = lr1;
    }
    if (kh == 0) {
        #pragma unroll
        for (int nt = 0; nt < 8; nt++) {
            *(float2*)(Osm + (16*rg + g    )*OSM_ST + 8*nt + 2*q) =
                make_float2(Oacc[nt][0], Oacc[nt][1]);
            *(float2*)(Osm + (16*rg + 8 + g)*OSM_ST + 8*nt + 2*q) =
                make_float2(Oacc[nt][2], Oacc[nt][3]);
        }
    }
    __syncthreads();

    if (kh == 1) {
        int row0 = 16*rg + g, row1 = row0 + 8;
        float inv0 = 1.0f / (lsumS[row0] + lsumS[128 + row0]);
        float inv1 = 1.0f / (lsumS[row1] + lsumS[128 + row1]);
        __half* ab = g_att + (size_t)b*SEQ*HID;
        int sA = s0 + row0, sB = s0 + row1;
        #pragma unroll
        for (int nt = 0; nt < 8; nt++) {
            float2 h0 = *(float2*)(Osm + row0*OSM_ST + 8*nt + 2*q);
            float2 h1 = *(float2*)(Osm + row1*OSM_ST + 8*nt + 2*q);
            float o0 = (Oacc[nt][0] + h0.x) * inv0;
            float o1 = (Oacc[nt][1] + h0.y) * inv0;
            float o2 = (Oacc[nt][2] + h1.x) * inv1;
            float o3 = (Oacc[nt][3] + h1.y) * inv1;
            int e = h*HD + 8*nt + 2*q;          // even
            size_t base = (size_t)(e >> 1)*HID;
            ab[base + sA]       = __float2half_rn(o0);
            ab[base + SEQ + sA] = __float2half_rn(o1);
            ab[base + sB]       = __float2half_rn(o2);
            ab[base + SEQ + sB] = __float2half_rn(o3);
        }
    }
}

// ---------------------------------------------------------------------------
extern "C" void kernel_launch(void* const* d_in, const int* in_sizes, int n_in,
                              void* d_out, int out_size)
{
    const float* x  = (const float*)d_in[0];
    const float* Wq = (const float*)d_in[1];
    const float* bq = (const float*)d_in[2];
    const float* Wk = (const float*)d_in[3];
    const float* bk = (const float*)d_in[4];
    const float* Wv = (const float*)d_in[5];
    const float* bv = (const float*)d_in[6];
    const float* Wo = (const float*)d_in[7];
    const float* bo = (const float*)d_in[8];
    float* out = (float*)d_out;

    cudaFuncSetAttribute(qkv_kernel,
                         cudaFuncAttributeMaxDynamicSharedMemorySize, GEMM_SMEM);
    cudaFuncSetAttribute(oproj_kernel,
                         cudaFuncAttributeMaxDynamicSharedMemorySize, GEMM_SMEM);
    cudaFuncSetAttribute(attn_kernel,
                         cudaFuncAttributeMaxDynamicSharedMemorySize, ATTN_SMEM);

    round_x_kernel<<<1024, 256>>>(x);
    transw_kernel<<<dim3(16,16,4), 256>>>(Wq, Wk, Wv, Wo);

    qkv_kernel<<<dim3(8,16,3), 256, GEMM_SMEM>>>(bq, bk, bv);

    attn_kernel<<<128, 512, ATTN_SMEM>>>();

    oproj_kernel<<<dim3(8,16), 256, GEMM_SMEM>>>(bo, out);
}

// round 7
// speedup vs baseline: 7.1547x; 1.2035x over previous
#include <cuda_runtime.h>
#include <cuda_fp16.h>
#include <cstdint>

#define HID 1024
#define SEQ 512
#define BATCH 2
#define NH 16
#define HD 64
#define ROWS (BATCH*SEQ)
#define NKEY (SEQ*NH)
#define NT 128

// Scratch (device globals)
__device__ __half g_qh[ROWS*HID];            // Q pre-scaled by 0.125*log2(e)
__device__ __half g_kh[ROWS*HID];            // K, [b][j][d]
__device__ __half g_vt[BATCH*HD*NKEY];       // V^T, [b][dd][j]
__device__ __half g_att[ROWS*HID];           // scrambled attention output
__device__ __half g_xh[ROWS*HID];            // x in fp16
__device__ __half g_wh[4*HID*HID];           // W^T in fp16: [z][n][k]

#define QSCALE 0.18033688f                   // 0.125 * log2(e)

// ---------------------------------------------------------------------------
__device__ __forceinline__ uint32_t h2bits(__half2 h){ return *(uint32_t*)&h; }
__device__ __forceinline__ void mma16(float* c, const uint32_t* a, uint32_t b0, uint32_t b1){
    asm volatile("mma.sync.aligned.m16n8k16.row.col.f32.f16.f16.f32 "
                 "{%0,%1,%2,%3},{%4,%5,%6,%7},{%8,%9},{%0,%1,%2,%3};"
                 : "+f"(c[0]),"+f"(c[1]),"+f"(c[2]),"+f"(c[3])
                 : "r"(a[0]),"r"(a[1]),"r"(a[2]),"r"(a[3]),"r"(b0),"r"(b1));
}
__device__ __forceinline__ void ldsm4(uint32_t* r, uint32_t addr){
    asm volatile("ldmatrix.sync.aligned.m8n8.x4.shared.b16 {%0,%1,%2,%3}, [%4];"
                 : "=r"(r[0]),"=r"(r[1]),"=r"(r[2]),"=r"(r[3]) : "r"(addr));
}
__device__ __forceinline__ float ex2(float x){
    float r; asm("ex2.approx.f32 %0, %1;" : "=f"(r) : "f"(x)); return r;
}
__device__ __forceinline__ void cp16(uint32_t dst, const void* src){
    asm volatile("cp.async.cg.shared.global [%0], [%1], 16;" :: "r"(dst), "l"(src));
}
__device__ __forceinline__ uint32_t smem_u32(const void* p){
    uint32_t a;
    asm("{ .reg .u64 t; cvta.to.shared.u64 t, %1; cvt.u32.u64 %0, t; }" : "=r"(a) : "l"(p));
    return a;
}
#define CP_COMMIT() asm volatile("cp.async.commit_group;")
#define CP_WAIT0()  asm volatile("cp.async.wait_group 0;")

// ---------------------------------------------------------------------------
// x -> fp16. grid 1024, 256 thr.
// ---------------------------------------------------------------------------
__global__ __launch_bounds__(256)
void round_x_kernel(const float* __restrict__ x)
{
    size_t i = ((size_t)blockIdx.x*256 + threadIdx.x)*4;
    float4 v = *(const float4*)(x + i);
    __half2 lo = __floats2half2_rn(v.x, v.y);
    __half2 hi = __floats2half2_rn(v.z, v.w);
    *(uint2*)(g_xh + i) = make_uint2(h2bits(lo), h2bits(hi));
}

// ---------------------------------------------------------------------------
// W[k][n] -> W^T fp16 [z][n][k]. grid (16,16,4), 256 thr.
// ---------------------------------------------------------------------------
__global__ __launch_bounds__(256)
void transw_kernel(const float* __restrict__ Wq, const float* __restrict__ Wk,
                   const float* __restrict__ Wv, const float* __restrict__ Wo)
{
    __shared__ float ts[64][65];
    const int z = blockIdx.z;
    const float* W = (z==0)?Wq:(z==1)?Wk:(z==2)?Wv:Wo;
    const int k0 = blockIdx.x*64, n0 = blockIdx.y*64;
    const int tid = threadIdx.x;

    #pragma unroll
    for (int t = 0; t < 4; t++) {
        int idx = tid + 256*t;
        int r = idx >> 4, c4 = (idx & 15) << 2;
        float4 v = *(const float4*)(W + (size_t)(k0+r)*HID + n0 + c4);
        ts[r][c4] = v.x; ts[r][c4+1] = v.y; ts[r][c4+2] = v.z; ts[r][c4+3] = v.w;
    }
    __syncthreads();
    #pragma unroll
    for (int t = 0; t < 4; t++) {
        int idx = tid + 256*t;
        int r = idx >> 4, c4 = (idx & 15) << 2;
        __half2 lo = __floats2half2_rn(ts[c4][r],   ts[c4+1][r]);
        __half2 hi = __floats2half2_rn(ts[c4+2][r], ts[c4+3][r]);
        *(uint2*)(g_wh + (size_t)z*HID*HID + (size_t)(n0+r)*HID + k0 + c4) =
            make_uint2(h2bits(lo), h2bits(hi));
    }
}

// ---------------------------------------------------------------------------
// fp16 mma GEMM (unchanged from R5 except Q scale constant).
// ---------------------------------------------------------------------------
#define AST 40
#define BST 40
#define ASZ (64*AST)
#define BSZ (128*BST)
#define GEMM_SMEM ((2*ASZ + 2*BSZ)*2)

__device__ __forceinline__ void gemm_fp16_body(const __half* __restrict__ A,
                                               const __half* __restrict__ Wt,
                                               const float* __restrict__ bias,
                                               int mode, float* __restrict__ outf)
{
    extern __shared__ __align__(16) char smc[];
    __half* sh = (__half*)smc;
    const uint32_t sb = smem_u32(sh);
    __half* Asb[2] = { sh, sh + ASZ };
    __half* Bsb[2] = { sh + 2*ASZ, sh + 2*ASZ + BSZ };
    const uint32_t au[2] = { sb, sb + ASZ*2u };
    const uint32_t bu[2] = { sb + 2u*ASZ*2u, sb + (2u*ASZ + BSZ)*2u };

    const int tid = threadIdx.x;
    const int w = tid >> 5, lane = tid & 31;
    const int g = lane >> 2, q = lane & 3;
    const int wr = w >> 2, wc = w & 3;
    const int m0 = blockIdx.y*64, n0 = blockIdx.x*128;

    float cacc[2][4][4];
    #pragma unroll
    for (int mf = 0; mf < 2; mf++)
        #pragma unroll
        for (int nf = 0; nf < 4; nf++)
            #pragma unroll
            for (int j = 0; j < 4; j++) cacc[mf][nf][j] = 0.f;

    {
        int ar = tid >> 2, ac = (tid & 3) << 3;
        cp16(au[0] + (ar*AST + ac)*2u, A + (size_t)(m0+ar)*HID + ac);
        #pragma unroll
        for (int t = 0; t < 2; t++) {
            int c = tid + 256*t;
            int br = c >> 2, bc = (c & 3) << 3;
            cp16(bu[0] + (br*BST + bc)*2u, Wt + (size_t)(n0+br)*HID + bc);
        }
        CP_COMMIT();
    }

    for (int kt = 0; kt < HID/32; kt++) {
        CP_WAIT0();
        __syncthreads();
        if (kt + 1 < HID/32) {
            int nb = (kt+1) & 1, k0 = (kt+1)*32;
            int ar = tid >> 2, ac = (tid & 3) << 3;
            cp16(au[nb] + (ar*AST + ac)*2u, A + (size_t)(m0+ar)*HID + k0 + ac);
            #pragma unroll
            for (int t = 0; t < 2; t++) {
                int c = tid + 256*t;
                int br = c >> 2, bc = (c & 3) << 3;
                cp16(bu[nb] + (br*BST + bc)*2u, Wt + (size_t)(n0+br)*HID + k0 + bc);
            }
            CP_COMMIT();
        }
        const __half* Ab = Asb[kt & 1];
        const __half* Bb = Bsb[kt & 1];

        #pragma unroll
        for (int kk = 0; kk < 2; kk++) {
            uint32_t af[2][4], bf[4][2];
            #pragma unroll
            for (int mf = 0; mf < 2; mf++) {
                int r0 = 32*wr + 16*mf;
                af[mf][0] = h2bits(*(const __half2*)(Ab + (r0+g  )*AST + 16*kk + 2*q));
                af[mf][1] = h2bits(*(const __half2*)(Ab + (r0+8+g)*AST + 16*kk + 2*q));
                af[mf][2] = h2bits(*(const __half2*)(Ab + (r0+g  )*AST + 16*kk + 8 + 2*q));
                af[mf][3] = h2bits(*(const __half2*)(Ab + (r0+8+g)*AST + 16*kk + 8 + 2*q));
            }
            #pragma unroll
            for (int nf = 0; nf < 4; nf++) {
                int col = 32*wc + 8*nf + g;
                bf[nf][0] = h2bits(*(const __half2*)(Bb + col*BST + 16*kk + 2*q));
                bf[nf][1] = h2bits(*(const __half2*)(Bb + col*BST + 16*kk + 8 + 2*q));
            }
            #pragma unroll
            for (int mf = 0; mf < 2; mf++)
                #pragma unroll
                for (int nf = 0; nf < 4; nf++)
                    mma16(cacc[mf][nf], af[mf], bf[nf][0], bf[nf][1]);
        }
    }

    #pragma unroll
    for (int mf = 0; mf < 2; mf++) {
        #pragma unroll
        for (int rr = 0; rr < 2; rr++) {
            int row = m0 + 32*wr + 16*mf + 8*rr + g;
            #pragma unroll
            for (int nf = 0; nf < 4; nf++) {
                int col = n0 + 32*wc + 8*nf + 2*q;
                float o0 = cacc[mf][nf][rr*2]   + __ldg(bias + col);
                float o1 = cacc[mf][nf][rr*2+1] + __ldg(bias + col + 1);
                if (mode == 0) {
                    __half2 h = __floats2half2_rn(o0*QSCALE, o1*QSCALE);
                    *(uint32_t*)(g_qh + (size_t)row*HID + col) = h2bits(h);
                } else if (mode == 1) {
                    __half2 h = __floats2half2_rn(o0, o1);
                    *(uint32_t*)(g_kh + (size_t)row*HID + col) = h2bits(h);
                } else if (mode == 2) {
                    int hh = col >> 6, dd = col & 63;
                    int s = row & 511, bb = row >> 9;
                    __half* dst = g_vt + (size_t)bb*HD*NKEY + s*16 + hh;
                    dst[(size_t)dd*NKEY]     = __float2half_rn(o0);
                    dst[(size_t)(dd+1)*NKEY] = __float2half_rn(o1);
                } else {
                    *(float2*)(outf + (size_t)row*HID + col) = make_float2(o0, o1);
                }
            }
        }
    }
}

__global__ __launch_bounds__(256)
void qkv_kernel(const float* __restrict__ bq, const float* __restrict__ bk,
                const float* __restrict__ bv)
{
    int z = blockIdx.z;
    const float* bias = (z == 0) ? bq : (z == 1) ? bk : bv;
    gemm_fp16_body(g_xh, g_wh + (size_t)z*HID*HID, bias, z, nullptr);
}

__global__ __launch_bounds__(256)
void oproj_kernel(const float* __restrict__ bo, float* __restrict__ out)
{
    gemm_fp16_body(g_att, g_wh + (size_t)3*HID*HID, bo, 3, out);
}

// ---------------------------------------------------------------------------
// fp16 mma flash attention: 256 CTAs (64-row Q tiles) x 256 thr = 8 warps.
// Warp: rg=w&3 (16 rows), kh=w>>2 (32-key half). LDSM fragment feed.
// smem: K[2][64][72] + Vt[2][64][72] halves = 36864 B (+ lsum) -> 2 CTAs/SM.
// ---------------------------------------------------------------------------
#define KSTH 72
#define KBUF (64*KSTH)
#define OSM_ST 66
#define ATTN_SMEM (4*KBUF*2 + 1024)

__global__ __launch_bounds__(256)
void attn_kernel()
{
    extern __shared__ __align__(16) char smc[];
    __half* sh = (__half*)smc;
    const uint32_t sb = smem_u32(sh);
    const uint32_t ku[2] = { sb, sb + KBUF*2u };
    const uint32_t vu[2] = { sb + 2u*KBUF*2u, sb + 3u*KBUF*2u };
    float* lsumS = (float*)(smc + 4*KBUF*2);
    float* Osm   = (float*)smc;

    const int tid = threadIdx.x;
    const int w = tid >> 5, lane = tid & 31;
    const int g = lane >> 2, q = lane & 3;
    const int lr = lane & 7, lm = lane >> 3;
    const int rg = w & 3, kh = w >> 2;
    const int bx = blockIdx.x;
    const int b  = bx >> 7;
    const int h  = (bx >> 3) & 15;
    const int s0 = (bx & 7) << 6;

    const __half* kb0 = g_kh + (size_t)b*SEQ*HID;     // [8192][64]
    const __half* vt0 = g_vt + (size_t)b*HD*NKEY;     // [64][8192]

    // prefetch coords: 512 16B-chunks per tile (8 per 64-half row), 2 per thread
    const int pr0 = tid >> 3, pc0 = (tid & 7) << 3;   // rows 0..31
    const int pr1 = pr0 + 32, pc1 = pc0;              // rows 32..63

    cp16(ku[0] + (pr0*KSTH + pc0)*2u, kb0 + (size_t)pr0*HD + pc0);
    cp16(ku[0] + (pr1*KSTH + pc1)*2u, kb0 + (size_t)pr1*HD + pc1);
    cp16(vu[0] + (pr0*KSTH + pc0)*2u, vt0 + (size_t)pr0*NKEY + pc0);
    cp16(vu[0] + (pr1*KSTH + pc1)*2u, vt0 + (size_t)pr1*NKEY + pc1);
    CP_COMMIT();

    // Q fragments from gmem (pre-scaled fp16)
    uint32_t qf[4][4];
    {
        const __half* qb = g_qh + (size_t)(b*SEQ + s0)*HID + h*HD;
        const __half* q0 = qb + (size_t)(16*rg + g)*HID;
        const __half* q1 = qb + (size_t)(16*rg + 8 + g)*HID;
        #pragma unroll
        for (int kt = 0; kt < 4; kt++) {
            qf[kt][0] = h2bits(*(const __half2*)(q0 + 16*kt + 2*q));
            qf[kt][1] = h2bits(*(const __half2*)(q1 + 16*kt + 2*q));
            qf[kt][2] = h2bits(*(const __half2*)(q0 + 16*kt + 8 + 2*q));
            qf[kt][3] = h2bits(*(const __half2*)(q1 + 16*kt + 8 + 2*q));
        }
    }

    // per-lane LDSM base offsets (bytes)
    const uint32_t koff = (uint32_t)(((32*kh + lr)*KSTH + 16*(lm >> 1) + 8*(lm & 1))*2);
    const uint32_t voff = (uint32_t)(((8*(lm >> 1) + lr)*KSTH + 32*kh + 8*(lm & 1))*2);

    float Oacc[8][4];
    #pragma unroll
    for (int nt = 0; nt < 8; nt++)
        #pragma unroll
        for (int j = 0; j < 4; j++) Oacc[nt][j] = 0.f;
    float lr0 = 0.f, lr1 = 0.f;

    for (int jt = 0; jt < NT; jt++) {
        CP_WAIT0();
        __syncthreads();
        if (jt + 1 < NT) {
            int nb = (jt+1) & 1;
            const __half* kp = kb0 + (size_t)(jt+1)*64*HD;
            const __half* vp = vt0 + (jt+1)*64;
            cp16(ku[nb] + (pr0*KSTH + pc0)*2u, kp + (size_t)pr0*HD + pc0);
            cp16(ku[nb] + (pr1*KSTH + pc1)*2u, kp + (size_t)pr1*HD + pc1);
            cp16(vu[nb] + (pr0*KSTH + pc0)*2u, vp + (size_t)pr0*NKEY + pc0);
            cp16(vu[nb] + (pr1*KSTH + pc1)*2u, vp + (size_t)pr1*NKEY + pc1);
            CP_COMMIT();
        }
        const uint32_t kcur = ku[jt & 1] + koff;
        const uint32_t vcur = vu[jt & 1] + voff;

        // ---- S = Q @ K^T : 16 rows x 32 keys ----
        float p[4][4];
        #pragma unroll
        for (int c = 0; c < 4; c++)
            #pragma unroll
            for (int j = 0; j < 4; j++) p[c][j] = 0.f;

        #pragma unroll
        for (int c = 0; c < 4; c++) {
            uint32_t kf[8];   // per kt: [b0, b1]
            ldsm4(kf,     kcur + (uint32_t)(c*8*KSTH*2));
            ldsm4(kf + 4, kcur + (uint32_t)(c*8*KSTH*2 + 64));
            #pragma unroll
            for (int kt = 0; kt < 4; kt++)
                mma16(p[c], qf[kt], kf[2*kt], kf[2*kt+1]);
        }

        // ---- P = ex2(S); pack fp16; sums over rounded values ----
        uint32_t pk[4][2];
        #pragma unroll
        for (int c = 0; c < 4; c++) {
            __half2 h0 = __floats2half2_rn(ex2(p[c][0]), ex2(p[c][1]));
            __half2 h1 = __floats2half2_rn(ex2(p[c][2]), ex2(p[c][3]));
            pk[c][0] = h2bits(h0);
            pk[c][1] = h2bits(h1);
            float2 f0 = __half22float2(h0);
            float2 f1 = __half22float2(h1);
            lr0 += f0.x + f0.y;
            lr1 += f1.x + f1.y;
        }

        // ---- O += P @ V ----
        #pragma unroll
        for (int u = 0; u < 2; u++) {
            uint32_t pa[4] = { pk[2*u][0], pk[2*u][1], pk[2*u+1][0], pk[2*u+1][1] };
            #pragma unroll
            for (int np = 0; np < 4; np++) {
                uint32_t vf[4];   // nt=2np: b0,b1 ; nt=2np+1: b0,b1
                ldsm4(vf, vcur + (uint32_t)((np*16*KSTH + u*16)*2));
                mma16(Oacc[2*np],     pa, vf[0], vf[1]);
                mma16(Oacc[2*np + 1], pa, vf[2], vf[3]);
            }
        }
    }

    // ---- reduce lsum over q lanes; combine key-halves via smem ----
    lr0 += __shfl_xor_sync(0xffffffffu, lr0, 1);
    lr0 += __shfl_xor_sync(0xffffffffu, lr0, 2);
    lr1 += __shfl_xor_sync(0xffffffffu, lr1, 1);
    lr1 += __shfl_xor_sync(0xffffffffu, lr1, 2);

    __syncthreads();   // all K/V reads done before Osm reuse
    if (q == 0) {
        lsumS[kh*64 + 16*rg + g]     = lr0;
        lsumS[kh*64 + 16*rg + 8 + g] = lr1;
    }
    if (kh == 0) {
        #pragma unroll
        for (int nt = 0; nt < 8; nt++) {
            *(float2*)(Osm + (16*rg + g    )*OSM_ST + 8*nt + 2*q) =
                make_float2(Oacc[nt][0], Oacc[nt][1]);
            *(float2*)(Osm + (16*rg + 8 + g)*OSM_ST + 8*nt + 2*q) =
                make_float2(Oacc[nt][2], Oacc[nt][3]);
        }
    }
    __syncthreads();

    if (kh == 1) {
        int row0 = 16*rg + g, row1 = row0 + 8;
        float inv0 = 1.0f / (lsumS[row0] + lsumS[64 + row0]);
        float inv1 = 1.0f / (lsumS[row1] + lsumS[64 + row1]);
        __half* ab = g_att + (size_t)b*SEQ*HID;
        int sA = s0 + row0, sB = s0 + row1;
        #pragma unroll
        for (int nt = 0; nt < 8; nt++) {
            float2 h0 = *(float2*)(Osm + row0*OSM_ST + 8*nt + 2*q);
            float2 h1 = *(float2*)(Osm + row1*OSM_ST + 8*nt + 2*q);
            float o0 = (Oacc[nt][0] + h0.x) * inv0;
            float o1 = (Oacc[nt][1] + h0.y) * inv0;
            float o2 = (Oacc[nt][2] + h1.x) * inv1;
            float o3 = (Oacc[nt][3] + h1.y) * inv1;
            int e = h*HD + 8*nt + 2*q;
            size_t base = (size_t)(e >> 1)*HID;
            ab[base + sA]       = __float2half_rn(o0);
            ab[base + SEQ + sA] = __float2half_rn(o1);
            ab[base + sB]       = __float2half_rn(o2);
            ab[base + sB + SEQ] = __float2half_rn(o3);
        }
    }
}

// ---------------------------------------------------------------------------
extern "C" void kernel_launch(void* const* d_in, const int* in_sizes, int n_in,
                              void* d_out, int out_size)
{
    const float* x  = (const float*)d_in[0];
    const float* Wq = (const float*)d_in[1];
    const float* bq = (const float*)d_in[2];
    const float* Wk = (const float*)d_in[3];
    const float* bk = (const float*)d_in[4];
    const float* Wv = (const float*)d_in[5];
    const float* bv = (const float*)d_in[6];
    const float* Wo = (const float*)d_in[7];
    const float* bo = (const float*)d_in[8];
    float* out = (float*)d_out;

    cudaFuncSetAttribute(qkv_kernel,
                         cudaFuncAttributeMaxDynamicSharedMemorySize, GEMM_SMEM);
    cudaFuncSetAttribute(oproj_kernel,
                         cudaFuncAttributeMaxDynamicSharedMemorySize, GEMM_SMEM);
    cudaFuncSetAttribute(attn_kernel,
                         cudaFuncAttributeMaxDynamicSharedMemorySize, ATTN_SMEM);

    round_x_kernel<<<1024, 256>>>(x);
    transw_kernel<<<dim3(16,16,4), 256>>>(Wq, Wk, Wv, Wo);

    qkv_kernel<<<dim3(8,16,3), 256, GEMM_SMEM>>>(bq, bk, bv);

    attn_kernel<<<256, 256, ATTN_SMEM>>>();

    oproj_kernel<<<dim3(8,16), 256, GEMM_SMEM>>>(bo, out);
}